// round 2
// baseline (speedup 1.0000x reference)
#include <cuda_runtime.h>
#include <cuda_bf16.h>
#include <cstdint>

#define B_   4
#define T_   512
#define D_   256
#define H_   8
#define BH_  32
#define MTOK 2048
#define N3_  6144
#define SCALE_ 0.0625f   // 1/sqrt(256)

// ---------------- scratch (static device globals; no runtime alloc) ----------------
__device__ __align__(256) __nv_bfloat16 g_xb [MTOK * D_];
__device__ __align__(256) __nv_bfloat16 g_wqvb[N3_ * D_];
__device__ __align__(256) __nv_bfloat16 g_fwb [D_ * D_];
__device__ __align__(256) float          g_q  [BH_ * T_ * D_];          // [b,h,tq,d] fp32
__device__ __align__(256) __nv_bfloat16 g_vfT[BH_ * D_ * T_];           // [b,h,d,tq]
__device__ __align__(256) __nv_bfloat16 g_vbT[BH_ * D_ * T_];           // [b,h,d,tk]
__device__ __align__(256) float          g_sc [(size_t)BH_ * T_ * T_];  // [slab][tq][tk]
__device__ __align__(256) float          g_scT[(size_t)BH_ * T_ * T_];  // [slab][tk][tq]
__device__ __align__(256) __nv_bfloat16 g_pa [(size_t)BH_ * T_ * T_];   // softmax(g_sc) rows
__device__ __align__(256) __nv_bfloat16 g_paT[(size_t)BH_ * T_ * T_];   // softmax(g_scT) rows
__device__ __align__(256) float          g_bb [BH_ * T_ * D_];          // [slab][tq][d]
__device__ __align__(256) float          g_bf [BH_ * T_ * D_];          // [slab][tk][d]
__device__ __align__(256) __nv_bfloat16 g_y1 [MTOK * D_];

// ---------------- fp32<->bf16 prep ----------------
__global__ void k_convert(const float* __restrict__ x,
                          const float* __restrict__ wqv,
                          const float* __restrict__ fw) {
    int i = blockIdx.x * 256 + threadIdx.x;       // grid covers N3_*D_ = 1572864
    if (i < N3_ * D_)  g_wqvb[i] = __float2bfloat16(wqv[i]);
    if (i < MTOK * D_) g_xb[i]   = __float2bfloat16(x[i]);
    if (i < D_ * D_)   g_fwb[i]  = __float2bfloat16(fw[i]);
}

// ---------------- bf16 mma core: 64x64 block tile, C = A(MxK) * B(NxK)^T ----------------
#define LDS_K 40   // padded smem K-stride (elements) -> conflict-free frag loads

__device__ __forceinline__ void mma16816(float* c, const uint32_t* a, const uint32_t* b) {
    asm volatile(
        "mma.sync.aligned.m16n8k16.row.col.f32.bf16.bf16.f32 "
        "{%0,%1,%2,%3}, {%4,%5,%6,%7}, {%8,%9}, {%0,%1,%2,%3};\n"
        : "+f"(c[0]), "+f"(c[1]), "+f"(c[2]), "+f"(c[3])
        : "r"(a[0]), "r"(a[1]), "r"(a[2]), "r"(a[3]), "r"(b[0]), "r"(b[1]));
}

// block: 256 threads = 8 warps as 2(M) x 4(N); warp tile 32x16
__device__ __forceinline__ void gemm_core(
    const __nv_bfloat16* __restrict__ A, int lda,
    const __nv_bfloat16* __restrict__ Bm, int ldb,
    int m0, int n0, int K,
    __nv_bfloat16* sA, __nv_bfloat16* sB,
    float acc[2][2][4])
{
    int tid  = threadIdx.x;
    int warp = tid >> 5, lane = tid & 31;
    int wm = warp >> 2, wn = warp & 3;
    int lr = tid >> 2;           // 0..63
    int lc = (tid & 3) * 8;      // 0,8,16,24

    #pragma unroll
    for (int i = 0; i < 2; i++)
        #pragma unroll
        for (int j = 0; j < 2; j++)
            #pragma unroll
            for (int r = 0; r < 4; r++) acc[i][j][r] = 0.f;

    for (int k0 = 0; k0 < K; k0 += 32) {
        *(uint4*)&sA[lr * LDS_K + lc] = *(const uint4*)&A[(size_t)(m0 + lr) * lda + k0 + lc];
        *(uint4*)&sB[lr * LDS_K + lc] = *(const uint4*)&Bm[(size_t)(n0 + lr) * ldb + k0 + lc];
        __syncthreads();
        #pragma unroll
        for (int ks = 0; ks < 2; ks++) {
            uint32_t af[2][4], bfr[2][2];
            int arow = wm * 32 + (lane >> 2);
            int acol = ks * 16 + (lane & 3) * 2;
            #pragma unroll
            for (int i = 0; i < 2; i++) {
                const __nv_bfloat16* p = &sA[(arow + i * 16) * LDS_K + acol];
                af[i][0] = *(const uint32_t*)(p);
                af[i][1] = *(const uint32_t*)(p + 8 * LDS_K);
                af[i][2] = *(const uint32_t*)(p + 8);
                af[i][3] = *(const uint32_t*)(p + 8 * LDS_K + 8);
            }
            int brow = wn * 16 + (lane >> 2);
            #pragma unroll
            for (int j = 0; j < 2; j++) {
                const __nv_bfloat16* p = &sB[(brow + j * 8) * LDS_K + acol];
                bfr[j][0] = *(const uint32_t*)(p);
                bfr[j][1] = *(const uint32_t*)(p + 8);
            }
            #pragma unroll
            for (int i = 0; i < 2; i++)
                #pragma unroll
                for (int j = 0; j < 2; j++)
                    mma16816(acc[i][j], af[i], bfr[j]);
        }
        __syncthreads();
    }
}

#define EPILOGUE_POS(i, j, r, rl, cl)                          \
    int rl = (warp >> 2) * 32 + (i) * 16 + (lane >> 2) + (((r) >> 1) * 8); \
    int cl = (warp & 3) * 16 + (j) * 8 + (lane & 3) * 2 + ((r) & 1);

// ---------------- v projection: [2048 x 6144] = xb @ wqvb^T, scatter to q/vfT/vbT ----------------
__global__ void k_vproj(const float* __restrict__ wqv_b) {
    __shared__ __align__(16) __nv_bfloat16 sA[64 * LDS_K];
    __shared__ __align__(16) __nv_bfloat16 sB[64 * LDS_K];
    int m0 = blockIdx.y * 64, n0 = blockIdx.x * 64;
    float acc[2][2][4];
    gemm_core(g_xb, D_, g_wqvb, D_, m0, n0, D_, sA, sB, acc);
    int tid = threadIdx.x, warp = tid >> 5, lane = tid & 31;
    #pragma unroll
    for (int i = 0; i < 2; i++)
        #pragma unroll
        for (int j = 0; j < 2; j++)
            #pragma unroll
            for (int r = 0; r < 4; r++) {
                EPILOGUE_POS(i, j, r, rl, cl);
                int m = m0 + rl, n = n0 + cl;
                float v = acc[i][j][r] + wqv_b[n];
                int b = m >> 9, t = m & 511;
                int h3 = n >> 8, d = n & 255;
                if (h3 < 8) {
                    g_q[(((size_t)(b * H_ + h3) * T_) + t) * D_ + d] = v;
                } else if (h3 < 16) {
                    g_vfT[(((size_t)(b * H_ + (h3 - 8)) * D_) + d) * T_ + t] = __float2bfloat16(v);
                } else {
                    g_vbT[(((size_t)(b * H_ + (h3 - 16)) * D_) + d) * T_ + t] = __float2bfloat16(v);
                }
            }
}

// ---------------- L1 scores, packed f32x2 version ----------------
// tile: 128(tq) x 64(tk) per block, 256 threads as 16(ty) x 16(tx), 8x4 per thread.
// f32x2 lanes hold (even d, odd d); k stored NEGATED in smem so diff is one add.f32x2.
// per 2 elems: add.f32x2 + 2x LOP3(abs) + add.f32x2  -> fma & alu pipes balanced.

#define SQ_P 129   // float2 row pitch (padded)
#define SK_P 65

__device__ __forceinline__ unsigned long long addf32x2(unsigned long long a, unsigned long long b) {
    unsigned long long d;
    asm("add.rn.f32x2 %0, %1, %2;" : "=l"(d) : "l"(a), "l"(b));
    return d;
}

__global__ void __launch_bounds__(256, 2)
k_scores(const float* __restrict__ x, const float* __restrict__ wk) {
    __shared__ __align__(16) float2 sq[16][SQ_P];  // [d-pair][tq] (pitch 129 -> only 128 used)
    __shared__ __align__(16) float2 sk[16][SK_P];  // [d-pair][tk] negated

    int slab = blockIdx.z;
    int b = slab >> 3, h = slab & 7;
    int tq0 = blockIdx.y * 128, tk0 = blockIdx.x * 64;
    int tid = threadIdx.x;
    int tx = tid & 15, ty = tid >> 4;

    const float* qbase = g_q + ((size_t)slab * T_ + tq0) * D_;
    const float* xbase = x + ((size_t)b * T_ + tk0) * D_;
    const float* wkh = wk + h * D_;

    unsigned long long acc[8][4];
    #pragma unroll
    for (int i = 0; i < 8; i++)
        #pragma unroll
        for (int j = 0; j < 4; j++) acc[i][j] = 0ull;   // bits of (+0.f, +0.f)

    // global-load thread mapping
    int qr = tid >> 1;               // 0..127
    int qc0 = (tid & 1) * 16;        // 0 or 16
    int kr = tid >> 2;               // 0..63
    int kc0 = (tid & 3) * 8;         // 0,8,16,24

    for (int k0 = 0; k0 < D_; k0 += 32) {
        __syncthreads();
        // q tile: 128 rows x 32 d
        #pragma unroll
        for (int u = 0; u < 4; u++) {
            float4 v = *(const float4*)&qbase[(size_t)qr * D_ + k0 + qc0 + u * 4];
            int p = (qc0 + u * 4) >> 1;
            sq[p][qr]     = make_float2(v.x, v.y);
            sq[p + 1][qr] = make_float2(v.z, v.w);
        }
        // k tile (negated): 64 rows x 32 d
        #pragma unroll
        for (int u = 0; u < 2; u++) {
            float4 v = *(const float4*)&xbase[(size_t)kr * D_ + k0 + kc0 + u * 4];
            float4 w = *(const float4*)&wkh[k0 + kc0 + u * 4];
            int p = (kc0 + u * 4) >> 1;
            sk[p][kr]     = make_float2(-v.x * w.x, -v.y * w.y);
            sk[p + 1][kr] = make_float2(-v.z * w.z, -v.w * w.w);
        }
        __syncthreads();

        #pragma unroll
        for (int c = 0; c < 16; c++) {
            unsigned long long q2[8], k2[4];
            #pragma unroll
            for (int i = 0; i < 8; i++)
                q2[i] = *(const unsigned long long*)&sq[c][i * 16 + ty];
            #pragma unroll
            for (int j = 0; j < 4; j++)
                k2[j] = *(const unsigned long long*)&sk[c][j * 16 + tx];
            #pragma unroll
            for (int i = 0; i < 8; i++)
                #pragma unroll
                for (int j = 0; j < 4; j++) {
                    unsigned long long d = addf32x2(q2[i], k2[j]);
                    d &= 0x7fffffff7fffffffULL;          // packed fabs (2x LOP3, alu pipe)
                    acc[i][j] = addf32x2(acc[i][j], d);
                }
        }
    }

    size_t base = (size_t)slab * T_ * T_;
    #pragma unroll
    for (int i = 0; i < 8; i++) {
        int tq = tq0 + i * 16 + ty;
        #pragma unroll
        for (int j = 0; j < 4; j++) {
            int tk = tk0 + j * 16 + tx;
            float2 f = *(float2*)&acc[i][j];
            float s = -SCALE_ * (f.x + f.y);
            g_sc [base + (size_t)tq * T_ + tk] = s;
            g_scT[base + (size_t)tk * T_ + tq] = s;
        }
    }
}

// ---------------- row softmax -> bf16 probs ----------------
__global__ void k_softmax(int which) {
    const float* S = which ? g_scT : g_sc;
    __nv_bfloat16* P = which ? g_paT : g_pa;
    int row = blockIdx.x, slab = blockIdx.y;
    const float* r = S + ((size_t)slab * T_ + row) * T_;
    int tid = threadIdx.x;                  // 128 threads
    float4 v = *(const float4*)&r[tid * 4];
    float m = fmaxf(fmaxf(v.x, v.y), fmaxf(v.z, v.w));
    #pragma unroll
    for (int o = 16; o; o >>= 1) m = fmaxf(m, __shfl_xor_sync(0xffffffffu, m, o));
    __shared__ float redm[4], reds[4];
    int warp = tid >> 5;
    if ((tid & 31) == 0) redm[warp] = m;
    __syncthreads();
    m = fmaxf(fmaxf(redm[0], redm[1]), fmaxf(redm[2], redm[3]));
    float e0 = __expf(v.x - m), e1 = __expf(v.y - m);
    float e2 = __expf(v.z - m), e3 = __expf(v.w - m);
    float s = (e0 + e1) + (e2 + e3);
    #pragma unroll
    for (int o = 16; o; o >>= 1) s += __shfl_xor_sync(0xffffffffu, s, o);
    if ((tid & 31) == 0) reds[warp] = s;
    __syncthreads();
    s = (reds[0] + reds[1]) + (reds[2] + reds[3]);
    float inv = 1.f / s;
    __nv_bfloat16* p = P + ((size_t)slab * T_ + row) * T_ + tid * 4;
    p[0] = __float2bfloat16(e0 * inv);
    p[1] = __float2bfloat16(e1 * inv);
    p[2] = __float2bfloat16(e2 * inv);
    p[3] = __float2bfloat16(e3 * inv);
}

// ---------------- AV GEMM per slab: C[t][d] = P(TxT) @ VT(DxT)^T ----------------
__global__ void k_av(int which) {
    const __nv_bfloat16* Pm = which ? g_paT : g_pa;
    const __nv_bfloat16* VT = which ? g_vfT : g_vbT;
    float* C = which ? g_bf : g_bb;
    __shared__ __align__(16) __nv_bfloat16 sA[64 * LDS_K];
    __shared__ __align__(16) __nv_bfloat16 sB[64 * LDS_K];
    int slab = blockIdx.z;
    int m0 = blockIdx.y * 64, n0 = blockIdx.x * 64;
    float acc[2][2][4];
    gemm_core(Pm + (size_t)slab * T_ * T_, T_,
              VT + (size_t)slab * D_ * T_, T_,
              m0, n0, T_, sA, sB, acc);
    int tid = threadIdx.x, warp = tid >> 5, lane = tid & 31;
    float* Cs = C + (size_t)slab * T_ * D_;
    #pragma unroll
    for (int i = 0; i < 2; i++)
        #pragma unroll
        for (int j = 0; j < 2; j++)
            #pragma unroll
            for (int r = 0; r < 4; r++) {
                EPILOGUE_POS(i, j, r, rl, cl);
                Cs[(size_t)(m0 + rl) * D_ + n0 + cl] = acc[i][j][r];
            }
}

// ---------------- head reduce + SiLU -> y1 (bf16) ----------------
__global__ void k_bo() {
    int idx = blockIdx.x * 256 + threadIdx.x;   // 0 .. 524287
    int bt = idx >> 8;                          // token
    int d = idx & 255;
    int b = bt >> 9, t = bt & 511;
    float s = 0.f;
    #pragma unroll
    for (int h = 0; h < H_; h++) {
        size_t o = (((size_t)(b * H_ + h) * T_) + t) * D_ + d;
        s += g_bf[o] + g_bb[o];
    }
    float sig = 1.f / (1.f + __expf(-1.702f * s));
    g_y1[idx] = __float2bfloat16(s * sig);
}

// ---------------- final fanin GEMM + bias + residual ----------------
__global__ void k_final(const float* __restrict__ x,
                        const float* __restrict__ fb,
                        float* __restrict__ out) {
    __shared__ __align__(16) __nv_bfloat16 sA[64 * LDS_K];
    __shared__ __align__(16) __nv_bfloat16 sB[64 * LDS_K];
    int m0 = blockIdx.y * 64, n0 = blockIdx.x * 64;
    float acc[2][2][4];
    gemm_core(g_y1, D_, g_fwb, D_, m0, n0, D_, sA, sB, acc);
    int tid = threadIdx.x, warp = tid >> 5, lane = tid & 31;
    #pragma unroll
    for (int i = 0; i < 2; i++)
        #pragma unroll
        for (int j = 0; j < 2; j++)
            #pragma unroll
            for (int r = 0; r < 4; r++) {
                EPILOGUE_POS(i, j, r, rl, cl);
                int m = m0 + rl, n = n0 + cl;
                out[(size_t)m * D_ + n] = acc[i][j][r] + fb[n] + x[(size_t)m * D_ + n];
            }
}

// ---------------- launch ----------------
extern "C" void kernel_launch(void* const* d_in, const int* in_sizes, int n_in,
                              void* d_out, int out_size) {
    const float* x       = (const float*)d_in[0];
    const float* wk      = (const float*)d_in[1];
    const float* wqv_w   = (const float*)d_in[2];
    const float* wqv_b   = (const float*)d_in[3];
    const float* fanin_w = (const float*)d_in[4];
    const float* fanin_b = (const float*)d_in[5];
    float* out = (float*)d_out;

    k_convert<<<6144, 256>>>(x, wqv_w, fanin_w);
    k_vproj<<<dim3(96, 32), 256>>>(wqv_b);
    k_scores<<<dim3(8, 4, 32), 256>>>(x, wk);
    k_softmax<<<dim3(512, 32), 128>>>(0);
    k_softmax<<<dim3(512, 32), 128>>>(1);
    k_av<<<dim3(4, 8, 32), 256>>>(0);
    k_av<<<dim3(4, 8, 32), 256>>>(1);
    k_bo<<<2048, 256>>>();
    k_final<<<dim3(4, 32), 256>>>(x, fanin_b, out);
}

// round 3
// speedup vs baseline: 1.6519x; 1.6519x over previous
#include <cuda_runtime.h>
#include <cuda_bf16.h>
#include <cstdint>

#define B_   4
#define T_   512
#define D_   256
#define H_   8
#define BH_  32
#define MTOK 2048
#define N3_  6144
#define SCALE_ 0.0625f                 // 1/sqrt(256)
#define LSCALE_ (0.0625f / 255.0f)     // logit per SAD count

typedef unsigned long long u64;
typedef unsigned int u32;
typedef unsigned short u16;
typedef unsigned char u8;

// ---------------- scratch (static device globals; no runtime alloc) ----------------
__device__ __align__(256) __nv_bfloat16 g_xb [MTOK * D_];
__device__ __align__(256) __nv_bfloat16 g_wqvb[N3_ * D_];
__device__ __align__(256) __nv_bfloat16 g_fwb [D_ * D_];
__device__ __align__(256) u8            g_q8 [BH_ * T_ * D_];           // quantized q
__device__ __align__(256) u8            g_k8 [BH_ * T_ * D_];           // quantized k
__device__ __align__(256) __nv_bfloat16 g_vfT[BH_ * D_ * T_];           // [b,h,d,t]
__device__ __align__(256) __nv_bfloat16 g_vbT[BH_ * D_ * T_];
__device__ __align__(256) u16           g_s16 [(size_t)BH_ * T_ * T_];  // SAD [slab][tq][tk]
__device__ __align__(256) u16           g_s16T[(size_t)BH_ * T_ * T_];  // SAD [slab][tk][tq]
__device__ __align__(256) __nv_bfloat16 g_pa [(size_t)BH_ * T_ * T_];
__device__ __align__(256) __nv_bfloat16 g_paT[(size_t)BH_ * T_ * T_];
__device__ __align__(256) float          g_bb [BH_ * T_ * D_];
__device__ __align__(256) float          g_bf [BH_ * T_ * D_];
__device__ __align__(256) __nv_bfloat16 g_y1 [MTOK * D_];

__device__ __forceinline__ u32 qu8(float v) {
    float f = fminf(fmaxf((v + 0.5f) * 255.f, 0.f), 255.f);
    return (u32)__float2int_rn(f);
}

__device__ __forceinline__ u32 vsad_acc(u32 a, u32 b, u32 c) {
    u32 d;
    asm("vabsdiff4.u32.u32.u32.add %0, %1, %2, %3;" : "=r"(d) : "r"(a), "r"(b), "r"(c));
    return d;
}

// ---------------- fp32->bf16 prep ----------------
__global__ void k_convert(const float* __restrict__ x,
                          const float* __restrict__ wqv,
                          const float* __restrict__ fw) {
    int i = blockIdx.x * 256 + threadIdx.x;
    if (i < N3_ * D_)  g_wqvb[i] = __float2bfloat16(wqv[i]);
    if (i < MTOK * D_) g_xb[i]   = __float2bfloat16(x[i]);
    if (i < D_ * D_)   g_fwb[i]  = __float2bfloat16(fw[i]);
}

// ---------------- quantize k = x*wk -> u8 ----------------
__global__ void k_quantk(const float* __restrict__ x, const float* __restrict__ wk) {
    int idx = blockIdx.x * 256 + threadIdx.x;    // 1,048,576 threads, 4 d each
    int d4 = idx & 63;
    int t  = (idx >> 6) & 511;
    int slab = idx >> 15;
    int b = slab >> 3, h = slab & 7;
    float4 xv = *(const float4*)&x[((size_t)(b * T_ + t)) * D_ + d4 * 4];
    float4 wv = *(const float4*)&wk[h * D_ + d4 * 4];
    uchar4 o;
    o.x = (u8)qu8(xv.x * wv.x);
    o.y = (u8)qu8(xv.y * wv.y);
    o.z = (u8)qu8(xv.z * wv.z);
    o.w = (u8)qu8(xv.w * wv.w);
    *(uchar4*)&g_k8[((size_t)(slab * T_ + t)) * D_ + d4 * 4] = o;
}

// ---------------- bf16 mma core: 64x64 block tile, C = A(MxK) * B(NxK)^T ----------------
#define LDS_K 40

__device__ __forceinline__ void mma16816(float* c, const u32* a, const u32* b) {
    asm volatile(
        "mma.sync.aligned.m16n8k16.row.col.f32.bf16.bf16.f32 "
        "{%0,%1,%2,%3}, {%4,%5,%6,%7}, {%8,%9}, {%0,%1,%2,%3};\n"
        : "+f"(c[0]), "+f"(c[1]), "+f"(c[2]), "+f"(c[3])
        : "r"(a[0]), "r"(a[1]), "r"(a[2]), "r"(a[3]), "r"(b[0]), "r"(b[1]));
}

__device__ __forceinline__ void gemm_core(
    const __nv_bfloat16* __restrict__ A, int lda,
    const __nv_bfloat16* __restrict__ Bm, int ldb,
    int m0, int n0, int K,
    __nv_bfloat16* sA, __nv_bfloat16* sB,
    float acc[2][2][4])
{
    int tid  = threadIdx.x;
    int warp = tid >> 5, lane = tid & 31;
    int wm = warp >> 2, wn = warp & 3;
    int lr = tid >> 2;
    int lc = (tid & 3) * 8;

    #pragma unroll
    for (int i = 0; i < 2; i++)
        #pragma unroll
        for (int j = 0; j < 2; j++)
            #pragma unroll
            for (int r = 0; r < 4; r++) acc[i][j][r] = 0.f;

    for (int k0 = 0; k0 < K; k0 += 32) {
        *(uint4*)&sA[lr * LDS_K + lc] = *(const uint4*)&A[(size_t)(m0 + lr) * lda + k0 + lc];
        *(uint4*)&sB[lr * LDS_K + lc] = *(const uint4*)&Bm[(size_t)(n0 + lr) * ldb + k0 + lc];
        __syncthreads();
        #pragma unroll
        for (int ks = 0; ks < 2; ks++) {
            u32 af[2][4], bfr[2][2];
            int arow = wm * 32 + (lane >> 2);
            int acol = ks * 16 + (lane & 3) * 2;
            #pragma unroll
            for (int i = 0; i < 2; i++) {
                const __nv_bfloat16* p = &sA[(arow + i * 16) * LDS_K + acol];
                af[i][0] = *(const u32*)(p);
                af[i][1] = *(const u32*)(p + 8 * LDS_K);
                af[i][2] = *(const u32*)(p + 8);
                af[i][3] = *(const u32*)(p + 8 * LDS_K + 8);
            }
            int brow = wn * 16 + (lane >> 2);
            #pragma unroll
            for (int j = 0; j < 2; j++) {
                const __nv_bfloat16* p = &sB[(brow + j * 8) * LDS_K + acol];
                bfr[j][0] = *(const u32*)(p);
                bfr[j][1] = *(const u32*)(p + 8);
            }
            #pragma unroll
            for (int i = 0; i < 2; i++)
                #pragma unroll
                for (int j = 0; j < 2; j++)
                    mma16816(acc[i][j], af[i], bfr[j]);
        }
        __syncthreads();
    }
}

#define EPILOGUE_POS(i, j, r, rl, cl)                          \
    int rl = (warp >> 2) * 32 + (i) * 16 + (lane >> 2) + (((r) >> 1) * 8); \
    int cl = (warp & 3) * 16 + (j) * 8 + (lane & 3) * 2 + ((r) & 1);

// ---------------- v projection: scatter to q8 / vfT / vbT ----------------
__global__ void k_vproj(const float* __restrict__ wqv_b) {
    __shared__ __align__(16) __nv_bfloat16 sA[64 * LDS_K];
    __shared__ __align__(16) __nv_bfloat16 sB[64 * LDS_K];
    int m0 = blockIdx.y * 64, n0 = blockIdx.x * 64;
    float acc[2][2][4];
    gemm_core(g_xb, D_, g_wqvb, D_, m0, n0, D_, sA, sB, acc);
    int tid = threadIdx.x, warp = tid >> 5, lane = tid & 31;
    int h3blk = n0 >> 8;    // same region for whole block (n0 is 64-aligned)
    #pragma unroll
    for (int i = 0; i < 2; i++)
        #pragma unroll
        for (int j = 0; j < 2; j++) {
            if (h3blk < 8) {
                // q path: quantize, pack r-pairs into u16 stores
                #pragma unroll
                for (int rp = 0; rp < 2; rp++) {
                    EPILOGUE_POS(i, j, rp * 2, rl, cl);
                    int m = m0 + rl, n = n0 + cl;
                    float v0 = acc[i][j][rp * 2]     + wqv_b[n];
                    float v1 = acc[i][j][rp * 2 + 1] + wqv_b[n + 1];
                    int b = m >> 9, t = m & 511;
                    int h3 = n >> 8, d = n & 255;
                    u32 p = qu8(v0) | (qu8(v1) << 8);
                    *(u16*)&g_q8[(((size_t)(b * H_ + h3) * T_) + t) * D_ + d] = (u16)p;
                }
            } else {
                #pragma unroll
                for (int r = 0; r < 4; r++) {
                    EPILOGUE_POS(i, j, r, rl, cl);
                    int m = m0 + rl, n = n0 + cl;
                    float v = acc[i][j][r] + wqv_b[n];
                    int b = m >> 9, t = m & 511;
                    int h3 = n >> 8, d = n & 255;
                    if (h3 < 16) {
                        g_vfT[(((size_t)(b * H_ + (h3 - 8)) * D_) + d) * T_ + t] = __float2bfloat16(v);
                    } else {
                        g_vbT[(((size_t)(b * H_ + (h3 - 16)) * D_) + d) * T_ + t] = __float2bfloat16(v);
                    }
                }
            }
        }
}

// ---------------- L1 scores via u8 SAD (vabsdiff4) ----------------
// block: 128(tq) x 64(tk), 256 threads, thread tile 8x4, d staged in chunks of 64.
__global__ void __launch_bounds__(256)
k_scores() {
    __shared__ union {
        struct { u64 q[8][128]; u64 k[8][64]; } ld;     // 12 KB
        u16 tr[128 * 68];                                // transpose stage (17 KB)
    } sm;

    int slab = blockIdx.z;
    int tq0 = blockIdx.y * 128, tk0 = blockIdx.x * 64;
    int tid = threadIdx.x;
    int tx = tid & 15, ty = tid >> 4;

    const u8* qg = g_q8 + ((size_t)slab * T_ + tq0) * D_;
    const u8* kg = g_k8 + ((size_t)slab * T_ + tk0) * D_;

    u32 acc[8][4];
    #pragma unroll
    for (int i = 0; i < 8; i++)
        #pragma unroll
        for (int j = 0; j < 4; j++) acc[i][j] = 0u;

    int qrow = tid >> 1, qhalf = tid & 1;    // q: 128 rows x 64B per stage
    int krow = tid >> 2, kq = tid & 3;       // k: 64 rows x 64B per stage

    for (int s = 0; s < 4; s++) {
        int k0 = s * 64;
        __syncthreads();
        {
            uint4 a = *(const uint4*)&qg[(size_t)qrow * D_ + k0 + qhalf * 32];
            uint4 b = *(const uint4*)&qg[(size_t)qrow * D_ + k0 + qhalf * 32 + 16];
            int c0 = qhalf * 4;
            sm.ld.q[c0 + 0][qrow] = ((u64)a.y << 32) | a.x;
            sm.ld.q[c0 + 1][qrow] = ((u64)a.w << 32) | a.z;
            sm.ld.q[c0 + 2][qrow] = ((u64)b.y << 32) | b.x;
            sm.ld.q[c0 + 3][qrow] = ((u64)b.w << 32) | b.z;
            uint4 c = *(const uint4*)&kg[(size_t)krow * D_ + k0 + kq * 16];
            sm.ld.k[kq * 2 + 0][krow] = ((u64)c.y << 32) | c.x;
            sm.ld.k[kq * 2 + 1][krow] = ((u64)c.w << 32) | c.z;
        }
        __syncthreads();

        #pragma unroll
        for (int c = 0; c < 8; c++) {
            u64 q2[8], k2[4];
            #pragma unroll
            for (int i = 0; i < 8; i++) q2[i] = sm.ld.q[c][i * 16 + ty];
            #pragma unroll
            for (int j = 0; j < 4; j++) k2[j] = sm.ld.k[c][j * 16 + tx];
            #pragma unroll
            for (int i = 0; i < 8; i++)
                #pragma unroll
                for (int j = 0; j < 4; j++) {
                    acc[i][j] = vsad_acc((u32)q2[i], (u32)k2[j], acc[i][j]);
                    acc[i][j] = vsad_acc((u32)(q2[i] >> 32), (u32)(k2[j] >> 32), acc[i][j]);
                }
        }
    }

    size_t base = (size_t)slab * T_ * T_;

    // phase A: transposed tile [tk][tq], pitch 132 -> g_s16T
    __syncthreads();
    #pragma unroll
    for (int i = 0; i < 8; i++)
        #pragma unroll
        for (int j = 0; j < 4; j++)
            sm.tr[(j * 16 + tx) * 132 + i * 16 + ty] = (u16)acc[i][j];
    __syncthreads();
    #pragma unroll
    for (int u = 0; u < 4; u++) {
        int idx = tid * 4 + u;            // 1024 chunks of 8B
        int row = idx >> 4, col = idx & 15;
        u64 v = *(const u64*)&sm.tr[row * 132 + col * 4];
        *(u64*)&g_s16T[base + (size_t)(tk0 + row) * T_ + tq0 + col * 4] = v;
    }

    // phase B: direct tile [tq][tk], pitch 68 -> g_s16
    __syncthreads();
    #pragma unroll
    for (int i = 0; i < 8; i++)
        #pragma unroll
        for (int j = 0; j < 4; j++)
            sm.tr[(i * 16 + ty) * 68 + j * 16 + tx] = (u16)acc[i][j];
    __syncthreads();
    #pragma unroll
    for (int u = 0; u < 8; u++) {
        int idx = tid * 8 + u;            // 2048 chunks of 8B
        int row = idx >> 4, col = idx & 15;
        u64 v = *(const u64*)&sm.tr[row * 68 + col * 4];
        *(u64*)&g_s16[base + (size_t)(tq0 + row) * T_ + tk0 + col * 4] = v;
    }
}

// ---------------- row softmax (u16 SAD in) -> bf16 probs ----------------
__global__ void k_softmax(int which) {
    const u16* S = which ? g_s16T : g_s16;
    __nv_bfloat16* P = which ? g_paT : g_pa;
    int row = blockIdx.x, slab = blockIdx.y;
    const u16* r = S + ((size_t)slab * T_ + row) * T_;
    int tid = threadIdx.x;                  // 128 threads
    u64 pk = *(const u64*)&r[tid * 4];
    float v0 = -LSCALE_ * (float)(pk & 0xffff);
    float v1 = -LSCALE_ * (float)((pk >> 16) & 0xffff);
    float v2 = -LSCALE_ * (float)((pk >> 32) & 0xffff);
    float v3 = -LSCALE_ * (float)(pk >> 48);
    float m = fmaxf(fmaxf(v0, v1), fmaxf(v2, v3));
    #pragma unroll
    for (int o = 16; o; o >>= 1) m = fmaxf(m, __shfl_xor_sync(0xffffffffu, m, o));
    __shared__ float redm[4], reds[4];
    int warp = tid >> 5;
    if ((tid & 31) == 0) redm[warp] = m;
    __syncthreads();
    m = fmaxf(fmaxf(redm[0], redm[1]), fmaxf(redm[2], redm[3]));
    float e0 = __expf(v0 - m), e1 = __expf(v1 - m);
    float e2 = __expf(v2 - m), e3 = __expf(v3 - m);
    float s = (e0 + e1) + (e2 + e3);
    #pragma unroll
    for (int o = 16; o; o >>= 1) s += __shfl_xor_sync(0xffffffffu, s, o);
    if ((tid & 31) == 0) reds[warp] = s;
    __syncthreads();
    s = (reds[0] + reds[1]) + (reds[2] + reds[3]);
    float inv = 1.f / s;
    __nv_bfloat16* p = P + ((size_t)slab * T_ + row) * T_ + tid * 4;
    p[0] = __float2bfloat16(e0 * inv);
    p[1] = __float2bfloat16(e1 * inv);
    p[2] = __float2bfloat16(e2 * inv);
    p[3] = __float2bfloat16(e3 * inv);
}

// ---------------- AV GEMM per slab ----------------
__global__ void k_av(int which) {
    const __nv_bfloat16* Pm = which ? g_paT : g_pa;
    const __nv_bfloat16* VT = which ? g_vfT : g_vbT;
    float* C = which ? g_bf : g_bb;
    __shared__ __align__(16) __nv_bfloat16 sA[64 * LDS_K];
    __shared__ __align__(16) __nv_bfloat16 sB[64 * LDS_K];
    int slab = blockIdx.z;
    int m0 = blockIdx.y * 64, n0 = blockIdx.x * 64;
    float acc[2][2][4];
    gemm_core(Pm + (size_t)slab * T_ * T_, T_,
              VT + (size_t)slab * D_ * T_, T_,
              m0, n0, T_, sA, sB, acc);
    int tid = threadIdx.x, warp = tid >> 5, lane = tid & 31;
    float* Cs = C + (size_t)slab * T_ * D_;
    #pragma unroll
    for (int i = 0; i < 2; i++)
        #pragma unroll
        for (int j = 0; j < 2; j++)
            #pragma unroll
            for (int r = 0; r < 4; r++) {
                EPILOGUE_POS(i, j, r, rl, cl);
                Cs[(size_t)(m0 + rl) * D_ + n0 + cl] = acc[i][j][r];
            }
}

// ---------------- head reduce + SiLU -> y1 (bf16) ----------------
__global__ void k_bo() {
    int idx = blockIdx.x * 256 + threadIdx.x;
    int bt = idx >> 8;
    int d = idx & 255;
    int b = bt >> 9, t = bt & 511;
    float s = 0.f;
    #pragma unroll
    for (int h = 0; h < H_; h++) {
        size_t o = (((size_t)(b * H_ + h) * T_) + t) * D_ + d;
        s += g_bf[o] + g_bb[o];
    }
    float sig = 1.f / (1.f + __expf(-1.702f * s));
    g_y1[idx] = __float2bfloat16(s * sig);
}

// ---------------- final fanin GEMM + bias + residual ----------------
__global__ void k_final(const float* __restrict__ x,
                        const float* __restrict__ fb,
                        float* __restrict__ out) {
    __shared__ __align__(16) __nv_bfloat16 sA[64 * LDS_K];
    __shared__ __align__(16) __nv_bfloat16 sB[64 * LDS_K];
    int m0 = blockIdx.y * 64, n0 = blockIdx.x * 64;
    float acc[2][2][4];
    gemm_core(g_y1, D_, g_fwb, D_, m0, n0, D_, sA, sB, acc);
    int tid = threadIdx.x, warp = tid >> 5, lane = tid & 31;
    #pragma unroll
    for (int i = 0; i < 2; i++)
        #pragma unroll
        for (int j = 0; j < 2; j++)
            #pragma unroll
            for (int r = 0; r < 4; r++) {
                EPILOGUE_POS(i, j, r, rl, cl);
                int m = m0 + rl, n = n0 + cl;
                out[(size_t)m * D_ + n] = acc[i][j][r] + fb[n] + x[(size_t)m * D_ + n];
            }
}

// ---------------- launch ----------------
extern "C" void kernel_launch(void* const* d_in, const int* in_sizes, int n_in,
                              void* d_out, int out_size) {
    const float* x       = (const float*)d_in[0];
    const float* wk      = (const float*)d_in[1];
    const float* wqv_w   = (const float*)d_in[2];
    const float* wqv_b   = (const float*)d_in[3];
    const float* fanin_w = (const float*)d_in[4];
    const float* fanin_b = (const float*)d_in[5];
    float* out = (float*)d_out;

    k_convert<<<6144, 256>>>(x, wqv_w, fanin_w);
    k_quantk<<<4096, 256>>>(x, wk);
    k_vproj<<<dim3(96, 32), 256>>>(wqv_b);
    k_scores<<<dim3(8, 4, 32), 256>>>();
    k_softmax<<<dim3(512, 32), 128>>>(0);
    k_softmax<<<dim3(512, 32), 128>>>(1);
    k_av<<<dim3(4, 8, 32), 256>>>(0);
    k_av<<<dim3(4, 8, 32), 256>>>(1);
    k_bo<<<2048, 256>>>();
    k_final<<<dim3(4, 32), 256>>>(x, fanin_b, out);
}